// round 5
// baseline (speedup 1.0000x reference)
#include <cuda_runtime.h>

#define NBLOCKS 1184  // 148 SMs * 8 CTAs

// Scratch (no device allocation allowed anywhere).
__device__ float        g_partials[NBLOCKS];
__device__ unsigned int g_ticket = 0;

__device__ __forceinline__ float hsum4(float4 v) {
    return (v.x + v.y) + (v.z + v.w);
}

// Sum one tensor of n4 float4s with 8-way batched loads for MLP.
__device__ __forceinline__ float sum_tensor(const float4* __restrict__ p, long n4,
                                            long tid, long stride)
{
    float s0 = 0.f, s1 = 0.f, s2 = 0.f, s3 = 0.f;
    float s4 = 0.f, s5 = 0.f, s6 = 0.f, s7 = 0.f;
    long i = tid;
    const long step8 = stride * 8;
    for (; i + 7 * stride < n4; i += step8) {
        float4 v0 = p[i];
        float4 v1 = p[i + stride];
        float4 v2 = p[i + 2 * stride];
        float4 v3 = p[i + 3 * stride];
        float4 v4 = p[i + 4 * stride];
        float4 v5 = p[i + 5 * stride];
        float4 v6 = p[i + 6 * stride];
        float4 v7 = p[i + 7 * stride];
        s0 += hsum4(v0);
        s1 += hsum4(v1);
        s2 += hsum4(v2);
        s3 += hsum4(v3);
        s4 += hsum4(v4);
        s5 += hsum4(v5);
        s6 += hsum4(v6);
        s7 += hsum4(v7);
    }
    for (; i < n4; i += stride)
        s0 += hsum4(p[i]);
    return ((s0 + s1) + (s2 + s3)) + ((s4 + s5) + (s6 + s7));
}

__global__ void __launch_bounds__(256)
sum3_fused_kernel(const float* __restrict__ af, long na,
                  const float* __restrict__ bf, long nb,
                  const float* __restrict__ cf, long nc,
                  float* __restrict__ out)
{
    const float4* a = (const float4*)af;
    const float4* b = (const float4*)bf;
    const float4* c = (const float4*)cf;
    const long na4 = na / 4, nb4 = nb / 4, nc4 = nc / 4;

    const long stride = (long)gridDim.x * blockDim.x;
    const long tid    = (long)blockIdx.x * blockDim.x + threadIdx.x;

    float s = sum_tensor(a, na4, tid, stride)
            + sum_tensor(b, nb4, tid, stride)
            + sum_tensor(c, nc4, tid, stride);

    // Block reduce
    #pragma unroll
    for (int o = 16; o > 0; o >>= 1)
        s += __shfl_xor_sync(0xffffffffu, s, o);

    __shared__ float wsum[8];
    __shared__ bool  is_last;
    int lane = threadIdx.x & 31;
    int wid  = threadIdx.x >> 5;
    if (lane == 0) wsum[wid] = s;
    __syncthreads();

    if (threadIdx.x == 0) {
        float t = 0.0f;
        #pragma unroll
        for (int w = 0; w < 8; w++) t += wsum[w];
        g_partials[blockIdx.x] = t;
        __threadfence();  // make partial visible before taking ticket
        unsigned int n = atomicAdd(&g_ticket, 1u);
        is_last = (n == gridDim.x - 1);
    }
    __syncthreads();

    // Last-arriving block performs the deterministic final reduction.
    if (is_last) {
        __threadfence();  // observe all other blocks' partials
        float f = 0.0f;
        for (int i = threadIdx.x; i < NBLOCKS; i += blockDim.x)
            f += g_partials[i];

        #pragma unroll
        for (int o = 16; o > 0; o >>= 1)
            f += __shfl_xor_sync(0xffffffffu, f, o);

        __shared__ float fw[8];
        if (lane == 0) fw[wid] = f;
        __syncthreads();

        if (threadIdx.x == 0) {
            float t = 0.0f;
            #pragma unroll
            for (int w = 0; w < 8; w++) t += fw[w];
            // Scalar remainders (n % 4) — no-op for these shapes, safe for variants.
            for (long i = na4 * 4; i < na; i++) t += af[i];
            for (long i = nb4 * 4; i < nb; i++) t += bf[i];
            for (long i = nc4 * 4; i < nc; i++) t += cf[i];
            out[0] = t;
            g_ticket = 0;  // reset for next graph replay
        }
    }
}

extern "C" void kernel_launch(void* const* d_in, const int* in_sizes, int n_in,
                              void* d_out, int out_size)
{
    const float* a = (const float*)d_in[0];
    const float* b = (const float*)d_in[1];
    const float* c = (const float*)d_in[2];

    sum3_fused_kernel<<<NBLOCKS, 256>>>(a, (long)in_sizes[0],
                                        b, (long)in_sizes[1],
                                        c, (long)in_sizes[2],
                                        (float*)d_out);
}

// round 16
// speedup vs baseline: 1.0430x; 1.0430x over previous
#include <cuda_runtime.h>

#define NBLOCKS 888   // 148 SMs * 6 CTAs -> exactly one wave at 6 CTAs/SM

// Scratch (no device allocation allowed anywhere).
__device__ float        g_partials[NBLOCKS];
__device__ unsigned int g_ticket = 0;

__device__ __forceinline__ float hsum4(float4 v) {
    return (v.x + v.y) + (v.z + v.w);
}

// Sum one tensor of n4 float4s with 4-way batched loads (MLP=4, low reg pressure).
// 32-bit indexing: element counts fit in uint (max ~43M), saves register pairs.
__device__ __forceinline__ float sum_tensor(const float4* __restrict__ p, unsigned n4,
                                            unsigned tid, unsigned stride)
{
    float s0 = 0.f, s1 = 0.f, s2 = 0.f, s3 = 0.f;
    unsigned i = tid;
    const unsigned step4 = stride * 4u;
    for (; i + 3u * stride < n4; i += step4) {
        float4 v0 = p[i];
        float4 v1 = p[i + stride];
        float4 v2 = p[i + 2u * stride];
        float4 v3 = p[i + 3u * stride];
        s0 += hsum4(v0);
        s1 += hsum4(v1);
        s2 += hsum4(v2);
        s3 += hsum4(v3);
    }
    for (; i < n4; i += stride)
        s0 += hsum4(p[i]);
    return (s0 + s1) + (s2 + s3);
}

__global__ void __launch_bounds__(256, 6)
sum3_fused_kernel(const float* __restrict__ af, unsigned na,
                  const float* __restrict__ bf, unsigned nb,
                  const float* __restrict__ cf, unsigned nc,
                  float* __restrict__ out)
{
    const float4* a = (const float4*)af;
    const float4* b = (const float4*)bf;
    const float4* c = (const float4*)cf;
    const unsigned na4 = na / 4u, nb4 = nb / 4u, nc4 = nc / 4u;

    const unsigned stride = gridDim.x * blockDim.x;
    const unsigned tid    = blockIdx.x * blockDim.x + threadIdx.x;

    float s = sum_tensor(a, na4, tid, stride)
            + sum_tensor(b, nb4, tid, stride)
            + sum_tensor(c, nc4, tid, stride);

    // Block reduce
    #pragma unroll
    for (int o = 16; o > 0; o >>= 1)
        s += __shfl_xor_sync(0xffffffffu, s, o);

    __shared__ float wsum[8];
    __shared__ bool  is_last;
    int lane = threadIdx.x & 31;
    int wid  = threadIdx.x >> 5;
    if (lane == 0) wsum[wid] = s;
    __syncthreads();

    if (threadIdx.x == 0) {
        float t = 0.0f;
        #pragma unroll
        for (int w = 0; w < 8; w++) t += wsum[w];
        g_partials[blockIdx.x] = t;
        __threadfence();  // make partial visible before taking ticket
        unsigned int n = atomicAdd(&g_ticket, 1u);
        is_last = (n == gridDim.x - 1);
    }
    __syncthreads();

    // Last-arriving block performs the deterministic final reduction.
    if (is_last) {
        __threadfence();  // observe all other blocks' partials
        float f = 0.0f;
        for (int i = threadIdx.x; i < NBLOCKS; i += blockDim.x)
            f += g_partials[i];

        #pragma unroll
        for (int o = 16; o > 0; o >>= 1)
            f += __shfl_xor_sync(0xffffffffu, f, o);

        __shared__ float fw[8];
        if (lane == 0) fw[wid] = f;
        __syncthreads();

        if (threadIdx.x == 0) {
            float t = 0.0f;
            #pragma unroll
            for (int w = 0; w < 8; w++) t += fw[w];
            // Scalar remainders (n % 4) — no-op for these shapes, safe for variants.
            for (unsigned i = na4 * 4u; i < na; i++) t += af[i];
            for (unsigned i = nb4 * 4u; i < nb; i++) t += bf[i];
            for (unsigned i = nc4 * 4u; i < nc; i++) t += cf[i];
            out[0] = t;
            g_ticket = 0;  // reset for next graph replay
        }
    }
}

extern "C" void kernel_launch(void* const* d_in, const int* in_sizes, int n_in,
                              void* d_out, int out_size)
{
    const float* a = (const float*)d_in[0];
    const float* b = (const float*)d_in[1];
    const float* c = (const float*)d_in[2];

    sum3_fused_kernel<<<NBLOCKS, 256>>>(a, (unsigned)in_sizes[0],
                                        b, (unsigned)in_sizes[1],
                                        c, (unsigned)in_sizes[2],
                                        (float*)d_out);
}